// round 6
// baseline (speedup 1.0000x reference)
#include <cuda_runtime.h>
#include <math.h>

#define BATCH 16
#define NPTS  4096
#define NSIDES (BATCH * 2)
#define NB 512
#define XMIN (-4.25f)
#define BW (8.5f / NB)                 // 0.016601...
#define INVBW ((float)NB / 8.5f)
#define W 6                            // window half-width in buckets (~0.10)

#define STH 512                        // scan threads
#define CHUNKS (NPTS / STH)            // 8
#define NPART (CHUNKS * BATCH * 2)     // 256

__device__ float  g_sx[NSIDES][NPTS];
__device__ float2 g_syz[NSIDES][NPTS];
__device__ int    g_bstart[NSIDES][NB + 1];
__device__ float  g_part[NPART];

__device__ __forceinline__ int bucket_of(float x) {
    int bk = (int)fmaxf((x - XMIN) * INVBW, 0.0f);
    return min(NB - 1, bk);
}

// Counting sort by x-bucket, one block per point set. Within-bucket order is
// nondeterministic (atomic scatter) but downstream results are invariant to
// it: min over a set + bucket-granular window/stop decisions.
__global__ __launch_bounds__(512)
void sort_kernel(const float* __restrict__ pred,
                 const float* __restrict__ target) {
    __shared__ int hist[NB], scanbuf[NB], cursor[NB];
    const int side = blockIdx.x;
    const int b = side >> 1, s = side & 1;
    const float* pts = (s == 0 ? pred : target) + (size_t)b * NPTS * 3;
    const int tid = threadIdx.x;

    hist[tid] = 0;
    __syncthreads();
    for (int p = tid; p < NPTS; p += 512)
        atomicAdd(&hist[bucket_of(pts[p * 3])], 1);
    __syncthreads();

    scanbuf[tid] = hist[tid];
    __syncthreads();
    for (int off = 1; off < NB; off <<= 1) {
        int v = (tid >= off) ? scanbuf[tid - off] : 0;
        __syncthreads();
        scanbuf[tid] += v;
        __syncthreads();
    }
    int st = scanbuf[tid] - hist[tid];
    cursor[tid] = st;
    g_bstart[side][tid] = st;
    if (tid == 0) g_bstart[side][NB] = NPTS;
    __syncthreads();

    for (int p = tid; p < NPTS; p += 512) {
        float x = pts[p * 3 + 0];
        float y = pts[p * 3 + 1];
        float z = pts[p * 3 + 2];
        int pos = atomicAdd(&cursor[bucket_of(x)], 1);
        g_sx[side][pos] = x;
        g_syz[side][pos] = make_float2(y, z);
    }
}

// Warp-uniform pruned NN scan. Phase A: all 32 lanes sweep the warp-union
// contiguous rank window with BROADCAST shared loads (round-1 structure).
// Phase B: rare per-lane outward bucket walk with exact edge-bound stop.
__global__ __launch_bounds__(STH)
void scan_kernel() {
    __shared__ float  sx[NPTS];    // 16KB
    __shared__ float2 syz[NPTS];   // 32KB  (48KB total; sx reused for reduce)

    const int chunk = blockIdx.x;
    const int b     = blockIdx.y;
    const int dir   = blockIdx.z;
    const int srcSide = b * 2 + dir;
    const int tgtSide = b * 2 + (dir ^ 1);

    for (int p = threadIdx.x; p < NPTS; p += STH) {
        sx[p]  = g_sx[tgtSide][p];
        syz[p] = g_syz[tgtSide][p];
    }
    __syncthreads();

    const int row = chunk * STH + threadIdx.x;
    const float kx  = g_sx[srcSide][row];
    const float2 kyz = g_syz[srcSide][row];
    const int* __restrict__ bst = g_bstart[tgtSide];

    const int hb = bucket_of(kx);
    const int lo_b = max(0,  __reduce_min_sync(0xFFFFFFFFu, hb) - W);
    const int hi_b = min(NB, __reduce_max_sync(0xFFFFFFFFu, hb) + W + 1);
    const int lo = bst[lo_b];
    const int hi = bst[hi_b];      // warp-uniform contiguous rank range

#define EVAL(h, mm) do {                                        \
        float dx = sx[h] - kx;                                  \
        float2 t = syz[h];                                      \
        float dy = t.x - kyz.x;                                 \
        float dz = t.y - kyz.y;                                 \
        float d2 = fmaf(dx, dx, fmaf(dy, dy, dz * dz));         \
        mm = fminf(mm, d2);                                     \
    } while (0)

    // Phase A: uniform bounds, broadcast loads, 4-way ILP
    float m0 = __int_as_float(0x7F800000), m1 = m0, m2 = m0, m3 = m0;
    int h = lo;
    for (; h + 4 <= hi; h += 4) {
        EVAL(h + 0, m0); EVAL(h + 1, m1); EVAL(h + 2, m2); EVAL(h + 3, m3);
    }
    for (; h < hi; h++) EVAL(h, m0);
    float m = fminf(fminf(m0, m1), fminf(m2, m3));

    // Phase B: per-lane outward walk (usually 1 bound check per side)
    int rs = hi_b, ls = lo_b - 1;
    bool rA = rs < NB, lA = ls >= 0;
    while (rA || lA) {
        if (rA) {
            float e = (XMIN + rs * BW) - kx;
            if (e * e > m) rA = false;
            else {
                for (int k = bst[rs]; k < bst[rs + 1]; k++) EVAL(k, m);
                rA = (++rs < NB);
            }
        }
        if (lA) {
            float e = kx - (XMIN + (ls + 1) * BW);
            if (e * e > m) lA = false;
            else {
                for (int k = bst[ls]; k < bst[ls + 1]; k++) EVAL(k, m);
                lA = (--ls >= 0);
            }
        }
    }
#undef EVAL

    float sroot = sqrtf(m);        // difference form: m >= 0

    __syncthreads();               // everyone done with sx
    sx[threadIdx.x] = sroot;
    __syncthreads();
    for (int o = STH / 2; o > 0; o >>= 1) {
        if (threadIdx.x < o) sx[threadIdx.x] += sx[threadIdx.x + o];
        __syncthreads();
    }
    if (threadIdx.x == 0)
        g_part[chunk + CHUNKS * (b + BATCH * dir)] = sx[0];
}

// Single tail kernel: deterministic fixed-slot combine + scale.
__global__ void reduce_kernel(float* __restrict__ out) {
    __shared__ float ssum[NPART];
    ssum[threadIdx.x] = g_part[threadIdx.x];
    __syncthreads();
    for (int o = NPART / 2; o > 0; o >>= 1) {
        if (threadIdx.x < o) ssum[threadIdx.x] += ssum[threadIdx.x + o];
        __syncthreads();
    }
    if (threadIdx.x == 0)
        out[0] = ssum[0] * (1.0f / (2.0f * BATCH * NPTS));
}

extern "C" void kernel_launch(void* const* d_in, const int* in_sizes, int n_in,
                              void* d_out, int out_size) {
    const float* pred   = (const float*)d_in[0];
    const float* target = (const float*)d_in[1];
    float* out = (float*)d_out;

    sort_kernel<<<NSIDES, 512>>>(pred, target);

    dim3 grid(CHUNKS, BATCH, 2);            // 8 x 16 x 2 = 256 blocks
    scan_kernel<<<grid, STH>>>();

    reduce_kernel<<<1, NPART>>>(out);
}

// round 7
// speedup vs baseline: 1.3685x; 1.3685x over previous
#include <cuda_runtime.h>
#include <math.h>

#define BATCH 16
#define NPTS  4096
#define NSIDES (BATCH * 2)
#define NB 512
#define XMIN (-4.25f)
#define BW (8.5f / NB)
#define INVBW ((float)NB / 8.5f)
#define W 6                            // initial window half-width (buckets)
#define EXT 4                          // buckets per warp-uniform extension

#define STH 256                        // scan threads
#define CHUNKS (NPTS / STH)            // 16
#define NPART (CHUNKS * BATCH * 2)     // 512

__device__ float  g_sx[NSIDES][NPTS];
__device__ float2 g_syz[NSIDES][NPTS];
__device__ int    g_bstart[NSIDES][NB + 1];
__device__ float  g_part[NPART];

__device__ __forceinline__ int bucket_of(float x) {
    int bk = (int)fmaxf((x - XMIN) * INVBW, 0.0f);
    return min(NB - 1, bk);
}

// Counting sort by x-bucket, one block (512 thr) per point set.
// Warp-hierarchical scan: 3 syncthreads instead of 18.
// Within-bucket order is nondeterministic (atomic scatter) but downstream
// results are invariant: min over a set + bucket-granular decisions.
__global__ __launch_bounds__(512)
void sort_kernel(const float* __restrict__ pred,
                 const float* __restrict__ target) {
    __shared__ int hist[NB], wsum[16], cursor[NB];
    const int side = blockIdx.x;
    const int b = side >> 1, s = side & 1;
    const float* pts = (s == 0 ? pred : target) + (size_t)b * NPTS * 3;
    const int tid = threadIdx.x, lane = tid & 31, warp = tid >> 5;

    hist[tid] = 0;
    __syncthreads();
    for (int p = tid; p < NPTS; p += 512)
        atomicAdd(&hist[bucket_of(pts[p * 3])], 1);
    __syncthreads();

    // hierarchical exclusive scan over 512 bucket counts
    int v = hist[tid];
    int incl = v;
#pragma unroll
    for (int o = 1; o < 32; o <<= 1) {
        int t = __shfl_up_sync(0xFFFFFFFFu, incl, o);
        if (lane >= o) incl += t;
    }
    if (lane == 31) wsum[warp] = incl;
    __syncthreads();
    if (warp == 0 && lane < 16) {
        int t = wsum[lane];
#pragma unroll
        for (int o = 1; o < 16; o <<= 1) {
            int u = __shfl_up_sync(0xFFFFu, t, o);
            if (lane >= o) t += u;
        }
        wsum[lane] = t;          // inclusive warp sums
    }
    __syncthreads();
    int excl = incl - v + (warp > 0 ? wsum[warp - 1] : 0);
    cursor[tid] = excl;
    g_bstart[side][tid] = excl;
    if (tid == 0) g_bstart[side][NB] = NPTS;
    __syncthreads();

    for (int p = tid; p < NPTS; p += 512) {
        float x = pts[p * 3 + 0];
        float y = pts[p * 3 + 1];
        float z = pts[p * 3 + 2];
        int pos = atomicAdd(&cursor[bucket_of(x)], 1);
        g_sx[side][pos] = x;
        g_syz[side][pos] = make_float2(y, z);
    }
}

// Fully warp-cooperative pruned scan: initial union+-W sweep, then
// warp-uniform window extensions until EVERY lane's bound is satisfied.
// All shared loads are broadcast; no per-lane serial walks.
__global__ __launch_bounds__(STH)
void scan_kernel() {
    __shared__ float  sx[NPTS];    // 16KB (reused for block reduce)
    __shared__ float2 syz[NPTS];   // 32KB

    const int chunk = blockIdx.x;
    const int b     = blockIdx.y;
    const int dir   = blockIdx.z;
    const int srcSide = b * 2 + dir;
    const int tgtSide = b * 2 + (dir ^ 1);

    for (int p = threadIdx.x; p < NPTS; p += STH) {
        sx[p]  = g_sx[tgtSide][p];
        syz[p] = g_syz[tgtSide][p];
    }
    __syncthreads();

    const int row = chunk * STH + threadIdx.x;
    const float kx  = g_sx[srcSide][row];
    const float2 kyz = g_syz[srcSide][row];
    const int* __restrict__ bst = g_bstart[tgtSide];

#define EVAL(h, mm) do {                                        \
        float dx = sx[h] - kx;                                  \
        float2 t = syz[h];                                      \
        float dy = t.x - kyz.x;                                 \
        float dz = t.y - kyz.y;                                 \
        float d2 = fmaf(dx, dx, fmaf(dy, dy, dz * dz));         \
        mm = fminf(mm, d2);                                     \
    } while (0)

    // Initial warp-union window
    const int hb = bucket_of(kx);
    int ls, rs;   // ls = next unscanned bucket left, rs = next right
    {
        const int lo_b = max(0,  __reduce_min_sync(0xFFFFFFFFu, hb) - W);
        const int hi_b = min(NB, __reduce_max_sync(0xFFFFFFFFu, hb) + W + 1);
        ls = lo_b - 1;
        rs = hi_b;
        const int lo = bst[lo_b], hi = bst[hi_b];
        float m0 = __int_as_float(0x7F800000), m1 = m0, m2 = m0, m3 = m0;
        int h = lo;
        for (; h + 4 <= hi; h += 4) {
            EVAL(h + 0, m0); EVAL(h + 1, m1);
            EVAL(h + 2, m2); EVAL(h + 3, m3);
        }
        for (; h < hi; h++) EVAL(h, m0);
        m0 = fminf(fminf(m0, m1), fminf(m2, m3));

        // Warp-uniform adaptive extension: whole warp extends while ANY lane
        // could still improve on that side. Extra evals only tighten the min.
        for (;;) {
            float eR = (XMIN + rs * BW) - kx;          // >= 0
            float eL = kx - (XMIN + (ls + 1) * BW);    // >= 0
            unsigned needR = __ballot_sync(0xFFFFFFFFu,
                                           (rs < NB) && (eR * eR <= m0));
            unsigned needL = __ballot_sync(0xFFFFFFFFu,
                                           (ls >= 0) && (eL * eL <= m0));
            if (!needR && !needL) break;
            if (needR) {
                int re = min(rs + EXT, NB);
                int e0 = bst[rs], e1 = bst[re];
                for (int k = e0; k + 2 <= e1; k += 2) {
                    EVAL(k, m0); EVAL(k + 1, m1);
                }
                if ((e1 - e0) & 1) EVAL(e1 - 1, m0);
                m0 = fminf(m0, m1);
                rs = re;
            }
            if (needL) {
                int le = max(ls - EXT + 1, 0);
                int e0 = bst[le], e1 = bst[ls + 1];
                for (int k = e0; k + 2 <= e1; k += 2) {
                    EVAL(k, m0); EVAL(k + 1, m1);
                }
                if ((e1 - e0) & 1) EVAL(e1 - 1, m0);
                m0 = fminf(m0, m1);
                ls = le - 1;
            }
        }
        m1 = m0;
        sx[0] = sx[0];   // no-op; keep structure simple
        // final per-lane result
        float sroot = sqrtf(m0);    // difference form: m0 >= 0

        __syncthreads();            // everyone done reading sx
        sx[threadIdx.x] = sroot;
    }
    __syncthreads();
    for (int o = STH / 2; o > 0; o >>= 1) {
        if (threadIdx.x < o) sx[threadIdx.x] += sx[threadIdx.x + o];
        __syncthreads();
    }
    if (threadIdx.x == 0)
        g_part[chunk + CHUNKS * (b + BATCH * dir)] = sx[0];
#undef EVAL
}

// Deterministic fixed-slot combine + scale.
__global__ void reduce_kernel(float* __restrict__ out) {
    __shared__ float ssum[NPART];
    ssum[threadIdx.x] = g_part[threadIdx.x];
    __syncthreads();
    for (int o = NPART / 2; o > 0; o >>= 1) {
        if (threadIdx.x < o) ssum[threadIdx.x] += ssum[threadIdx.x + o];
        __syncthreads();
    }
    if (threadIdx.x == 0)
        out[0] = ssum[0] * (1.0f / (2.0f * BATCH * NPTS));
}

extern "C" void kernel_launch(void* const* d_in, const int* in_sizes, int n_in,
                              void* d_out, int out_size) {
    const float* pred   = (const float*)d_in[0];
    const float* target = (const float*)d_in[1];
    float* out = (float*)d_out;

    sort_kernel<<<NSIDES, 512>>>(pred, target);

    dim3 grid(CHUNKS, BATCH, 2);            // 16 x 16 x 2 = 512 blocks
    scan_kernel<<<grid, STH>>>();

    reduce_kernel<<<1, NPART>>>(out);
}